// round 1
// baseline (speedup 1.0000x reference)
#include <cuda_runtime.h>
#include <stdint.h>

// Cl(8,0,0): N=256 components, 1024 multivector pairs (4 x 256), out [3,1024,256].
// gp[i]    = sum_j s(j, j^i) A[j] B[j^i]
// wedge    : subset j ⊆ i           (j & ~i == 0)
// inner    : (j & i)==0 || i ⊆ j    ((j&i)==0 || (i & ~j)==0)

#define NCOMP 256
#define G 8               // batch elements per block
#define BATCH_ELEMS 1024  // 4 * 256

// Packed sign bits: bit (k&31) of word [j*8 + (k>>5)] set iff sign(j,k) < 0.
__device__ unsigned int g_signbits[2048];

__global__ void pack_signs_kernel(const int* __restrict__ gp_j,
                                  const int* __restrict__ gp_k,
                                  const float* __restrict__ gp_s) {
    __shared__ unsigned int sh[2048];
    int t = threadIdx.x;             // 1024 threads
    sh[t] = 0u;
    sh[t + 1024] = 0u;
    __syncthreads();
    #pragma unroll
    for (int p = 0; p < 64; ++p) {
        int m = p * 1024 + t;
        float s = gp_s[m];
        if (s < 0.0f) {
            int j = gp_j[m];
            int k = gp_k[m];
            atomicOr(&sh[(j << 3) + (k >> 5)], 1u << (k & 31));
        }
    }
    __syncthreads();
    g_signbits[t] = sh[t];
    g_signbits[t + 1024] = sh[t + 1024];
}

__global__ __launch_bounds__(256) void clifford_kernel(
    const float* __restrict__ A,
    const float* __restrict__ B,
    float* __restrict__ out) {
    __shared__ float sA[G][NCOMP];
    __shared__ float sB[G][NCOMP];
    __shared__ unsigned int sW[2048];

    const int t = threadIdx.x;           // = output component i
    const int base = blockIdx.x * G;     // first batch element of this block

    #pragma unroll
    for (int g = 0; g < G; ++g) {
        sA[g][t] = A[(base + g) * NCOMP + t];
        sB[g][t] = B[(base + g) * NCOMP + t];
    }
    #pragma unroll
    for (int r = 0; r < 8; ++r)
        sW[r * 256 + t] = g_signbits[r * 256 + t];
    __syncthreads();

    const int i = t;
    float accg[G], accw[G], acci[G];
    #pragma unroll
    for (int g = 0; g < G; ++g) { accg[g] = 0.f; accw[g] = 0.f; acci[g] = 0.f; }

    #pragma unroll 8
    for (int j = 0; j < NCOMP; ++j) {
        const int k = j ^ i;
        const unsigned int w = sW[(j << 3) + (k >> 5)];
        const unsigned int sgn = ((w >> (k & 31)) & 1u) << 31;
        const bool pw = (j & ~i) == 0;                      // wedge: j subset of i
        const bool pi = ((j & i) == 0) | ((i & ~j) == 0);   // inner

        #pragma unroll
        for (int g = 0; g < G; ++g) {
            float as = __int_as_float(__float_as_int(sA[g][j]) ^ sgn);
            float v = as * sB[g][k];
            accg[g] += v;
            if (pw) accw[g] += v;
            if (pi) acci[g] += v;
        }
    }

    #pragma unroll
    for (int g = 0; g < G; ++g) {
        const int be = base + g;
        out[(0 * BATCH_ELEMS + be) * NCOMP + i] = accg[g];
        out[(1 * BATCH_ELEMS + be) * NCOMP + i] = accw[g];
        out[(2 * BATCH_ELEMS + be) * NCOMP + i] = acci[g];
    }
}

extern "C" void kernel_launch(void* const* d_in, const int* in_sizes, int n_in,
                              void* d_out, int out_size) {
    const float* A       = (const float*)d_in[0];
    const float* B       = (const float*)d_in[1];
    const int*   gp_j    = (const int*)d_in[2];
    const int*   gp_k    = (const int*)d_in[3];
    const float* gp_s    = (const float*)d_in[5];
    float* out = (float*)d_out;

    pack_signs_kernel<<<1, 1024>>>(gp_j, gp_k, gp_s);
    clifford_kernel<<<BATCH_ELEMS / G, NCOMP>>>(A, B, out);
}

// round 3
// speedup vs baseline: 1.7170x; 1.7170x over previous
#include <cuda_runtime.h>
#include <stdint.h>

// Cl(8,0,0): 256 components, 1024 multivectors (4x256), out [3,1024,256].
// For output component i: gp[i] = sum_j sign(j, j^i) * A[j] * B[j^i]
//   sign(j,k) = (-1)^{ sum_{p in j} popc(k & ((1<<p)-1)) }
//             = (-1)^{ popc( j & prefixparity(k) ) }
//   wedge mask: j & ~i == 0         (j subset of i)
//   inner mask: (j&i)==0 || (i&~j)==0
// Signs/masks are folded into per-j float coefficients (0 / +1 / -1) and the
// whole inner accumulation runs as packed f32x2 FMAs over G=8 batch elements.

#define NCOMP 256
#define G 8
#define BATCH_ELEMS 1024

typedef unsigned long long u64;

#define MUL2(out, a, b) \
    asm("mul.rn.f32x2 %0, %1, %2;" : "=l"(out) : "l"(a), "l"(b))
#define FMA2(out, a, b, c) \
    asm("fma.rn.f32x2 %0, %1, %2, %3;" : "=l"(out) : "l"(a), "l"(b), "l"(c))

__device__ __forceinline__ u64 pack2(float x) {
    u64 r;
    asm("mov.b64 %0, {%1, %1};" : "=l"(r) : "f"(x));
    return r;
}
__device__ __forceinline__ float2 unpack2(u64 v) {
    float2 f;
    asm("mov.b64 {%0, %1}, %2;" : "=f"(f.x), "=f"(f.y) : "l"(v));
    return f;
}

__global__ __launch_bounds__(128) void clifford_kernel(
    const float* __restrict__ A,
    const float* __restrict__ B,
    float* __restrict__ out) {
    // sA[j*8 + g]  : A components, g contiguous -> broadcast LDS.128 per j
    // sB[k*10 + g] : B components, stride 10 floats (pad 2) -> conflict-free
    //                LDS.64 gather over the XOR-coset of k
    __shared__ __align__(16) float sA[NCOMP * G];
    __shared__ __align__(16) float sB[NCOMP * 10];

    const int t = threadIdx.x;                 // 0..127
    const int bb = blockIdx.x >> 1;            // batch group (8 elems)
    const int ih = blockIdx.x & 1;             // i-half
    const int base = bb * G;
    const int i = ih * 128 + t;

    // Fill shared: coalesced gmem reads (j contiguous per iteration)
    #pragma unroll
    for (int r = 0; r < (NCOMP * G) / 128; ++r) {
        int idx = r * 128 + t;
        int j = idx & (NCOMP - 1);
        int g = idx >> 8;
        float a = A[(base + g) * NCOMP + j];
        float b = B[(base + g) * NCOMP + j];
        sA[j * 8 + g] = a;
        sB[j * 10 + g] = b;
    }
    __syncthreads();

    u64 accg[4], accw[4], acci[4];
    #pragma unroll
    for (int p = 0; p < 4; ++p) { accg[p] = 0ull; accw[p] = 0ull; acci[p] = 0ull; }

    const int noti = ~i;

    #pragma unroll 8
    for (int j = 0; j < NCOMP; ++j) {
        const int k = j ^ i;
        // prefix parity of k: bit p = XOR of k bits strictly below p
        unsigned x = (unsigned)k << 1;
        x ^= x << 1;
        x ^= x << 2;
        x ^= x << 4;
        const unsigned par = (unsigned)__popc(j & (int)x) & 1u;
        const float sgn = __int_as_float(0x3f800000u | (par << 31));
        const float wf = ((j & noti) == 0) ? sgn : 0.0f;
        const float nf = (((j & i) == 0) | ((i & ~j) == 0)) ? sgn : 0.0f;
        const u64 s2 = pack2(sgn);
        const u64 w2 = pack2(wf);
        const u64 n2 = pack2(nf);

        const u64* a2 = (const u64*)(sA + j * 8);        // broadcast
        const float* bp = sB + k * 10;

        #pragma unroll
        for (int p = 0; p < 4; ++p) {
            u64 av = a2[p];
            u64 bv = *(const u64*)(bp + 2 * p);
            u64 v;
            MUL2(v, av, bv);
            FMA2(accg[p], v, s2, accg[p]);
            FMA2(accw[p], v, w2, accw[p]);
            FMA2(acci[p], v, n2, acci[p]);
        }
    }

    #pragma unroll
    for (int p = 0; p < 4; ++p) {
        float2 g = unpack2(accg[p]);
        float2 w = unpack2(accw[p]);
        float2 n = unpack2(acci[p]);
        const int be0 = base + 2 * p;
        out[(0 * BATCH_ELEMS + be0) * NCOMP + i] = g.x;
        out[(0 * BATCH_ELEMS + be0 + 1) * NCOMP + i] = g.y;
        out[(1 * BATCH_ELEMS + be0) * NCOMP + i] = w.x;
        out[(1 * BATCH_ELEMS + be0 + 1) * NCOMP + i] = w.y;
        out[(2 * BATCH_ELEMS + be0) * NCOMP + i] = n.x;
        out[(2 * BATCH_ELEMS + be0 + 1) * NCOMP + i] = n.y;
    }
}

extern "C" void kernel_launch(void* const* d_in, const int* in_sizes, int n_in,
                              void* d_out, int out_size) {
    const float* A = (const float*)d_in[0];
    const float* B = (const float*)d_in[1];
    float* out = (float*)d_out;
    clifford_kernel<<<(BATCH_ELEMS / G) * 2, 128>>>(A, B, out);
}

// round 4
// speedup vs baseline: 2.0312x; 1.1830x over previous
#include <cuda_runtime.h>
#include <stdint.h>

// Cl(8,0,0): 256 components, 1024 multivectors (4x256), out [3,1024,256].
// gp[i] = sum_j sign(j, j^i) * A[j] * B[j^i]
//   sign(j,k) = (-1)^{popc(j & prefixparity(k))}
//   wedge: j & ~i == 0 ;  inner: (j&i)==0 || (i&~j)==0
// 512-thread blocks: 4 j-slices x 128 i-threads, G=8 batch elems per block,
// packed f32x2 math, smem tree reduction across slices.

#define NCOMP 256
#define G 8
#define BATCH_ELEMS 1024

typedef unsigned long long u64;

#define MUL2(out, a, b) \
    asm("mul.rn.f32x2 %0, %1, %2;" : "=l"(out) : "l"(a), "l"(b))
#define FMA2(out, a, b, c) \
    asm("fma.rn.f32x2 %0, %1, %2, %3;" : "=l"(out) : "l"(a), "l"(b), "l"(c))
#define ADD2(out, a, b) \
    asm("add.rn.f32x2 %0, %1, %2;" : "=l"(out) : "l"(a), "l"(b))

__device__ __forceinline__ u64 pack2(float x) {
    u64 r;
    asm("mov.b64 %0, {%1, %1};" : "=l"(r) : "f"(x));
    return r;
}
__device__ __forceinline__ float2 unpack2(u64 v) {
    float2 f;
    asm("mov.b64 {%0, %1}, %2;" : "=f"(f.x), "=f"(f.y) : "l"(v));
    return f;
}

// smem: phase 1: sA (256*8 f32 = 8192B) + sB (256*12 f32 = 12288B) = 20480B
//       phase 2 (reduction, after sync): 256 * 13 u64 = 26624B (aliased)
#define SMEM_BYTES 26624
#define RSTRIDE 13

__global__ __launch_bounds__(512, 2) void clifford_kernel(
    const float* __restrict__ A,
    const float* __restrict__ B,
    float* __restrict__ out) {
    __shared__ __align__(16) char smem_raw[SMEM_BYTES];
    float* sA = (float*)smem_raw;             // [j*8 + g]
    float* sB = (float*)(smem_raw + 8192);    // [k*12 + g], pad->16B-aligned rows

    const int tid = threadIdx.x;              // 0..511
    const int t = tid & 127;                  // i within half
    const int s = tid >> 7;                   // j-slice 0..3
    const int bb = blockIdx.x >> 1;
    const int ih = blockIdx.x & 1;
    const int base = bb * G;
    const int i = ih * 128 + t;

    // Coalesced load of 8 batch elems x 256 comps for A and B
    #pragma unroll
    for (int r = 0; r < (NCOMP * G) / 512; ++r) {
        int idx = r * 512 + tid;
        int j = idx & (NCOMP - 1);
        int g = idx >> 8;
        sA[j * 8 + g] = A[(base + g) * NCOMP + j];
        sB[j * 12 + g] = B[(base + g) * NCOMP + j];
    }
    __syncthreads();

    u64 accg[4], accw[4], acci[4];
    #pragma unroll
    for (int p = 0; p < 4; ++p) { accg[p] = 0ull; accw[p] = 0ull; acci[p] = 0ull; }

    const int noti = ~i;
    const int jbase = s * 64;

    #pragma unroll 8
    for (int jj = 0; jj < 64; ++jj) {
        const int j = jbase + jj;
        const int k = j ^ i;
        // prefix parity of k
        unsigned x = (unsigned)k << 1;
        x ^= x << 1;
        x ^= x << 2;
        x ^= x << 4;
        const unsigned par = (unsigned)__popc(j & (int)x) & 1u;
        const float sgn = __int_as_float(0x3f800000u | (par << 31));
        const float wf = ((j & noti) == 0) ? sgn : 0.0f;
        const float nf = (((j & i) == 0) | ((i & ~j) == 0)) ? sgn : 0.0f;
        const u64 s2 = pack2(sgn);
        const u64 w2 = pack2(wf);
        const u64 n2 = pack2(nf);

        const ulonglong2* ap = (const ulonglong2*)(sA + j * 8);   // broadcast
        const ulonglong2* bp = (const ulonglong2*)(sB + k * 12);  // gather
        ulonglong2 a01 = ap[0], a23 = ap[1];
        ulonglong2 b01 = bp[0], b23 = bp[1];
        u64 av[4] = {a01.x, a01.y, a23.x, a23.y};
        u64 bv[4] = {b01.x, b01.y, b23.x, b23.y};

        #pragma unroll
        for (int p = 0; p < 4; ++p) {
            u64 v;
            MUL2(v, av[p], bv[p]);
            FMA2(accg[p], v, s2, accg[p]);
            FMA2(accw[p], v, w2, accw[p]);
            FMA2(acci[p], v, n2, acci[p]);
        }
    }

    // Tree reduction across the 4 j-slices (smem aliased over sA/sB)
    __syncthreads();
    u64* red = (u64*)smem_raw;

    if (tid >= 256) {
        u64* dst = red + (tid - 256) * RSTRIDE;
        #pragma unroll
        for (int p = 0; p < 4; ++p) {
            dst[p] = accg[p]; dst[4 + p] = accw[p]; dst[8 + p] = acci[p];
        }
    }
    __syncthreads();
    if (tid < 256) {
        const u64* src = red + tid * RSTRIDE;
        #pragma unroll
        for (int p = 0; p < 4; ++p) {
            ADD2(accg[p], accg[p], src[p]);
            ADD2(accw[p], accw[p], src[4 + p]);
            ADD2(acci[p], acci[p], src[8 + p]);
        }
    }
    __syncthreads();
    if (tid >= 128 && tid < 256) {
        u64* dst = red + (tid - 128) * RSTRIDE;
        #pragma unroll
        for (int p = 0; p < 4; ++p) {
            dst[p] = accg[p]; dst[4 + p] = accw[p]; dst[8 + p] = acci[p];
        }
    }
    __syncthreads();
    if (tid < 128) {
        const u64* src = red + tid * RSTRIDE;
        #pragma unroll
        for (int p = 0; p < 4; ++p) {
            ADD2(accg[p], accg[p], src[p]);
            ADD2(accw[p], accw[p], src[4 + p]);
            ADD2(acci[p], acci[p], src[8 + p]);
        }
        #pragma unroll
        for (int p = 0; p < 4; ++p) {
            float2 g = unpack2(accg[p]);
            float2 w = unpack2(accw[p]);
            float2 n = unpack2(acci[p]);
            const int be0 = base + 2 * p;
            out[(0 * BATCH_ELEMS + be0) * NCOMP + i] = g.x;
            out[(0 * BATCH_ELEMS + be0 + 1) * NCOMP + i] = g.y;
            out[(1 * BATCH_ELEMS + be0) * NCOMP + i] = w.x;
            out[(1 * BATCH_ELEMS + be0 + 1) * NCOMP + i] = w.y;
            out[(2 * BATCH_ELEMS + be0) * NCOMP + i] = n.x;
            out[(2 * BATCH_ELEMS + be0 + 1) * NCOMP + i] = n.y;
        }
    }
}

extern "C" void kernel_launch(void* const* d_in, const int* in_sizes, int n_in,
                              void* d_out, int out_size) {
    const float* A = (const float*)d_in[0];
    const float* B = (const float*)d_in[1];
    float* out = (float*)d_out;
    clifford_kernel<<<(BATCH_ELEMS / G) * 2, 512>>>(A, B, out);
}